// round 4
// baseline (speedup 1.0000x reference)
#include <cuda_runtime.h>
#include <cuda_fp16.h>
#include <cstdint>

// Grouped GEMM out[16384,4096]: 8 groups of [2048x4096] @ w[g][4096x4096], fp32 io.
// Pass 1: fp32 -> fp16 scratch. Pass 2: fp16 HMMA (m16n8k16) GEMM with
// cp.async.bulk row copies (192 ops/k-tile vs 3072 for cp.async.cg) + mbarrier
// full/empty ring -> removes the LSU issue floor measured in round 3.

#define TOK   16384
#define INF   4096
#define OUTF  4096
#define NG    8

#define BM    128
#define BN    256
#define BK    64
#define KT    (INF / BK)          // 64 k-tiles

#define SAH   72                  // A smem row stride (halves): 144B
#define SBH   264                 // B smem row stride (halves): 528B
#define A_BYTES (BM * SAH * 2)    // 18432
#define B_BYTES (BK * SBH * 2)    // 33792
#define STAGE_BYTES (A_BYTES + B_BYTES)       // 52224
#define STAGES 4
#define SMEM_BYTES (1024 + STAGES * STAGE_BYTES)
#define NTHREADS 512
#define TX_BYTES (BM * BK * 2 + BK * BN * 2)  // 49152 real bytes per stage

__device__ __align__(16) __half g_xh[(size_t)TOK * INF];
__device__ __align__(16) __half g_wh[(size_t)NG * INF * OUTF];

// ---------------- pass 1: fp32 -> fp16 ----------------
__global__ void cvt_f32_f16(const float* __restrict__ src, __half* __restrict__ dst,
                            size_t n8) {
    size_t i = (size_t)blockIdx.x * blockDim.x + threadIdx.x;
    const size_t stride = (size_t)gridDim.x * blockDim.x;
    for (; i < n8; i += stride) {
        float4 v0 = reinterpret_cast<const float4*>(src)[2 * i];
        float4 v1 = reinterpret_cast<const float4*>(src)[2 * i + 1];
        __half2 h0 = __floats2half2_rn(v0.x, v0.y);
        __half2 h1 = __floats2half2_rn(v0.z, v0.w);
        __half2 h2 = __floats2half2_rn(v1.x, v1.y);
        __half2 h3 = __floats2half2_rn(v1.z, v1.w);
        uint4 u;
        u.x = *reinterpret_cast<uint32_t*>(&h0);
        u.y = *reinterpret_cast<uint32_t*>(&h1);
        u.z = *reinterpret_cast<uint32_t*>(&h2);
        u.w = *reinterpret_cast<uint32_t*>(&h3);
        reinterpret_cast<uint4*>(dst)[i] = u;
    }
}

// ---------------- pass 2: fp16 HMMA GEMM ----------------
__device__ __forceinline__ uint32_t smem_u32(const void* p) {
    uint32_t a;
    asm("{ .reg .u64 t; cvta.to.shared.u64 t, %1; cvt.u32.u64 %0, t; }"
        : "=r"(a) : "l"(p));
    return a;
}

__device__ __forceinline__ void bulk_cp(uint32_t dst, const void* src, uint32_t bytes,
                                        uint32_t mbar) {
    asm volatile(
        "cp.async.bulk.shared::cta.global.mbarrier::complete_tx::bytes [%0], [%1], %2, [%3];"
        :: "r"(dst), "l"(src), "r"(bytes), "r"(mbar) : "memory");
}

__device__ __forceinline__ void mbar_wait(uint32_t addr, uint32_t phase) {
    asm volatile(
        "{ .reg .pred P;\n"
        "WL_%=: mbarrier.try_wait.parity.acquire.cta.shared::cta.b64 P, [%0], %1, 0x989680;\n"
        "@P bra.uni WD_%=;\n"
        "bra.uni WL_%=;\n"
        "WD_%=: }\n" :: "r"(addr), "r"(phase) : "memory");
}

#define LDSM_X4(r0, r1, r2, r3, a)                                              \
    asm volatile("ldmatrix.sync.aligned.m8n8.x4.shared.b16 {%0,%1,%2,%3}, [%4];" \
                 : "=r"(r0), "=r"(r1), "=r"(r2), "=r"(r3) : "r"(a))

#define LDSM_X4T(r0, r1, r2, r3, a)                                                   \
    asm volatile("ldmatrix.sync.aligned.m8n8.x4.trans.shared.b16 {%0,%1,%2,%3}, [%4];" \
                 : "=r"(r0), "=r"(r1), "=r"(r2), "=r"(r3) : "r"(a))

__device__ __forceinline__ void mma16816(float* d, const uint32_t* a, const uint32_t* b) {
    asm volatile(
        "mma.sync.aligned.m16n8k16.row.col.f32.f16.f16.f32 "
        "{%0,%1,%2,%3}, {%4,%5,%6,%7}, {%8,%9}, {%0,%1,%2,%3};"
        : "+f"(d[0]), "+f"(d[1]), "+f"(d[2]), "+f"(d[3])
        : "r"(a[0]), "r"(a[1]), "r"(a[2]), "r"(a[3]), "r"(b[0]), "r"(b[1]));
}

extern "C" __global__ void __launch_bounds__(NTHREADS, 1)
grouped_gemm_f16(float* __restrict__ out) {
    extern __shared__ char sm[];
    const uint32_t smb = smem_u32(sm);
    const uint32_t dataB = smb + 1024;
    // hdr: full[s] at smb + s*8, empty[s] at smb + 32 + s*8

    const int t = threadIdx.x;
    const int lane = t & 31;
    const int wid = t >> 5;          // 16 warps: 4 (m) x 4 (n)
    const int wm = wid & 3;
    const int wn = wid >> 2;

    const int bid = blockIdx.x;
    const int nt = bid & 15;         // nt-inner: wave shares A panels in L2
    const int mt = bid >> 4;
    const int g  = mt >> 4;

    const __half* xg = g_xh + (size_t)mt * BM * INF;
    const __half* wg = g_wh + (size_t)g * INF * OUTF + (size_t)nt * BN;

    if (t == 0) {
#pragma unroll
        for (int s = 0; s < STAGES; s++) {
            asm volatile("mbarrier.init.shared.b64 [%0], 1;" :: "r"(smb + s * 8) : "memory");
            asm volatile("mbarrier.init.shared.b64 [%0], %1;"
                         :: "r"(smb + 32 + s * 8), "r"(NTHREADS) : "memory");
        }
    }
    __syncthreads();

    // Producer: warp 0. lane issues 4 A rows + 2 B rows per k-tile (bulk copies).
    auto produce = [&](int j) {
        const uint32_t sb = dataB + (uint32_t)(j & 3) * STAGE_BYTES;
        const uint32_t mb = smb + (j & 3) * 8;
        if (lane == 0)
            asm volatile("mbarrier.arrive.expect_tx.shared.b64 _, [%0], %1;"
                         :: "r"(mb), "r"((uint32_t)TX_BYTES) : "memory");
        __syncwarp();
#pragma unroll
        for (int i = 0; i < 4; i++) {
            int row = lane + 32 * i;
            bulk_cp(sb + (uint32_t)row * (SAH * 2),
                    xg + (size_t)row * INF + (size_t)j * BK, BK * 2, mb);
        }
#pragma unroll
        for (int i = 0; i < 2; i++) {
            int k = lane + 32 * i;
            bulk_cp(sb + A_BYTES + (uint32_t)k * (SBH * 2),
                    wg + (size_t)((size_t)j * BK + k) * OUTF, BN * 2, mb);
        }
    };

    if (wid == 0) {
        produce(0);
        produce(1);
        produce(2);
    }

    float acc[2][8][4];
#pragma unroll
    for (int mi = 0; mi < 2; mi++)
#pragma unroll
        for (int ni = 0; ni < 8; ni++)
#pragma unroll
            for (int q = 0; q < 4; q++) acc[mi][ni][q] = 0.0f;

    const uint32_t aOff =
        (uint32_t)(wm * 32 + (lane & 7) + ((lane >> 3) & 1) * 8) * (SAH * 2) +
        (uint32_t)((lane >> 4) & 1) * 16;
    const uint32_t bOff = A_BYTES +
        (uint32_t)((lane & 7) + ((lane >> 3) & 1) * 8) * (SBH * 2) +
        (uint32_t)(wn * 64 + ((lane >> 4) & 1) * 8) * 2;

    for (int kt = 0; kt < KT; kt++) {
        mbar_wait(smb + (kt & 3) * 8, (uint32_t)((kt >> 2) & 1));   // full

        const uint32_t stage = dataB + (uint32_t)(kt & 3) * STAGE_BYTES;
#pragma unroll
        for (int ks = 0; ks < 4; ks++) {
            uint32_t a[2][4], b[4][4];
#pragma unroll
            for (int mi = 0; mi < 2; mi++)
                LDSM_X4(a[mi][0], a[mi][1], a[mi][2], a[mi][3],
                        stage + aOff + (uint32_t)mi * (16 * SAH * 2) + (uint32_t)ks * 32);
#pragma unroll
            for (int np = 0; np < 4; np++)
                LDSM_X4T(b[np][0], b[np][1], b[np][2], b[np][3],
                         stage + bOff + (uint32_t)ks * (16 * SBH * 2) + (uint32_t)np * 32);
#pragma unroll
            for (int mi = 0; mi < 2; mi++)
#pragma unroll
                for (int np = 0; np < 4; np++) {
                    mma16816(acc[mi][2 * np],     a[mi], &b[np][0]);
                    mma16816(acc[mi][2 * np + 1], a[mi], &b[np][2]);
                }
        }

        // reads of this stage done -> signal empty
        asm volatile("mbarrier.arrive.shared.b64 _, [%0];"
                     :: "r"(smb + 32 + (kt & 3) * 8) : "memory");

        if (wid == 0) {
            int j = kt + 3;
            if (j < KT) {
                if (j >= 4)
                    mbar_wait(smb + 32 + (j & 3) * 8, (uint32_t)(((j - 4) >> 2) & 1));
                produce(j);
            }
        }
    }

    const int r0 = mt * BM + wm * 32 + (lane >> 2);
    const int c0 = nt * BN + wn * 64 + 2 * (lane & 3);
#pragma unroll
    for (int mi = 0; mi < 2; mi++)
#pragma unroll
        for (int ni = 0; ni < 8; ni++) {
            size_t base = (size_t)(r0 + mi * 16) * OUTF + c0 + ni * 8;
            *reinterpret_cast<float2*>(out + base) =
                make_float2(acc[mi][ni][0], acc[mi][ni][1]);
            *reinterpret_cast<float2*>(out + base + 8 * OUTF) =
                make_float2(acc[mi][ni][2], acc[mi][ni][3]);
        }
}

extern "C" void kernel_launch(void* const* d_in, const int* in_sizes, int n_in,
                              void* d_out, int out_size) {
    const float* x = (const float*)d_in[0];
    const float* w = (const float*)d_in[1];
    float* out = (float*)d_out;

    __half* xh = nullptr;
    __half* wh = nullptr;
    cudaGetSymbolAddress((void**)&xh, g_xh);
    cudaGetSymbolAddress((void**)&wh, g_wh);

    cvt_f32_f16<<<4096, 256>>>(x, xh, (size_t)TOK * INF / 8);
    cvt_f32_f16<<<8192, 256>>>(w, wh, (size_t)NG * INF * OUTF / 8);

    cudaFuncSetAttribute(grouped_gemm_f16,
                         cudaFuncAttributeMaxDynamicSharedMemorySize, SMEM_BYTES);
    dim3 grid((TOK / BM) * (OUTF / BN));   // 2048
    grouped_gemm_f16<<<grid, NTHREADS, SMEM_BYTES>>>(out);
}

// round 6
// speedup vs baseline: 3.3937x; 3.3937x over previous
#include <cuda_runtime.h>
#include <cuda_fp16.h>
#include <cstdint>

// Grouped GEMM out[16384,4096]: 8 groups of [2048x4096] @ w[g][4096x4096], fp32 io.
// Pass 1: fp32 -> fp16 scratch (DRAM-bound, ~80% peak).
// Pass 2: fp16 HMMA m16n8k16 GEMM. 256 threads, warp tile 64x64 -> halves the
// ldsm smem-read redundancy (192KB -> 128KB per k-tile) so the smem crossbar
// (~1408 cyc) drops below the tensor-pipe floor (2048 cyc).

#define TOK   16384
#define INF   4096
#define OUTF  4096
#define NG    8

#define BM    128
#define BN    256
#define BK    64
#define KT    (INF / BK)          // 64 k-tiles

#define SAH   72                  // A smem row stride (halves): 144B (bank step 4)
#define SBH   264                 // B smem row stride (halves): 528B (bank step 4)
#define A_BYTES (BM * SAH * 2)    // 18432
#define B_BYTES (BK * SBH * 2)    // 33792
#define STAGE_BYTES (A_BYTES + B_BYTES)       // 52224
#define STAGES 4
#define SMEM_BYTES (STAGES * STAGE_BYTES)     // 208896
#define NTHREADS 256

__device__ __align__(16) __half g_xh[(size_t)TOK * INF];
__device__ __align__(16) __half g_wh[(size_t)NG * INF * OUTF];

// ---------------- pass 1: fp32 -> fp16 ----------------
__global__ void cvt_f32_f16(const float* __restrict__ src, __half* __restrict__ dst,
                            size_t n8) {
    size_t i = (size_t)blockIdx.x * blockDim.x + threadIdx.x;
    const size_t stride = (size_t)gridDim.x * blockDim.x;
    for (; i < n8; i += stride) {
        float4 v0 = reinterpret_cast<const float4*>(src)[2 * i];
        float4 v1 = reinterpret_cast<const float4*>(src)[2 * i + 1];
        __half2 h0 = __floats2half2_rn(v0.x, v0.y);
        __half2 h1 = __floats2half2_rn(v0.z, v0.w);
        __half2 h2 = __floats2half2_rn(v1.x, v1.y);
        __half2 h3 = __floats2half2_rn(v1.z, v1.w);
        uint4 u;
        u.x = *reinterpret_cast<uint32_t*>(&h0);
        u.y = *reinterpret_cast<uint32_t*>(&h1);
        u.z = *reinterpret_cast<uint32_t*>(&h2);
        u.w = *reinterpret_cast<uint32_t*>(&h3);
        reinterpret_cast<uint4*>(dst)[i] = u;
    }
}

// ---------------- pass 2: fp16 HMMA GEMM ----------------
__device__ __forceinline__ uint32_t smem_u32(const void* p) {
    uint32_t a;
    asm("{ .reg .u64 t; cvta.to.shared.u64 t, %1; cvt.u32.u64 %0, t; }"
        : "=r"(a) : "l"(p));
    return a;
}

#define CPA16(dst, src) \
    asm volatile("cp.async.cg.shared.global [%0], [%1], 16;" :: "r"(dst), "l"(src))

#define LDSM_X4(r0, r1, r2, r3, a)                                              \
    asm volatile("ldmatrix.sync.aligned.m8n8.x4.shared.b16 {%0,%1,%2,%3}, [%4];" \
                 : "=r"(r0), "=r"(r1), "=r"(r2), "=r"(r3) : "r"(a))

#define LDSM_X4T(r0, r1, r2, r3, a)                                                   \
    asm volatile("ldmatrix.sync.aligned.m8n8.x4.trans.shared.b16 {%0,%1,%2,%3}, [%4];" \
                 : "=r"(r0), "=r"(r1), "=r"(r2), "=r"(r3) : "r"(a))

__device__ __forceinline__ void mma16816(float* d, const uint32_t* a, const uint32_t* b) {
    asm volatile(
        "mma.sync.aligned.m16n8k16.row.col.f32.f16.f16.f32 "
        "{%0,%1,%2,%3}, {%4,%5,%6,%7}, {%8,%9}, {%0,%1,%2,%3};"
        : "+f"(d[0]), "+f"(d[1]), "+f"(d[2]), "+f"(d[3])
        : "r"(a[0]), "r"(a[1]), "r"(a[2]), "r"(a[3]), "r"(b[0]), "r"(b[1]));
}

extern "C" __global__ void __launch_bounds__(NTHREADS, 1)
grouped_gemm_f16(float* __restrict__ out) {
    extern __shared__ char sm[];
    const uint32_t smb = smem_u32(sm);

    const int t = threadIdx.x;
    const int lane = t & 31;
    const int wid = t >> 5;          // 8 warps: 2 (m) x 4 (n)
    const int wm = wid & 1;          // 64-row warp tile
    const int wn = wid >> 1;         // 64-col warp tile

    const int bid = blockIdx.x;
    const int nt = bid & 15;         // nt-inner: wave shares A panels in L2
    const int mt = bid >> 4;
    const int g  = mt >> 4;

    const __half* xg = g_xh + (size_t)mt * BM * INF;
    const __half* wg = g_wh + (size_t)g * INF * OUTF + (size_t)nt * BN;

    auto load_tile = [&](int kt) {
        const uint32_t sb = smb + (uint32_t)(kt & 3) * STAGE_BYTES;
#pragma unroll
        for (int i = 0; i < 4; i++) {           // A: 1024 x 16B; id = row*8 + kc
            int id = t + i * NTHREADS;
            int row = id >> 3, kc = id & 7;
            CPA16(sb + (uint32_t)row * (SAH * 2) + (uint32_t)kc * 16,
                  xg + (size_t)row * INF + (size_t)kt * BK + kc * 8);
        }
#pragma unroll
        for (int i = 0; i < 8; i++) {           // B: 2048 x 16B; id = k*32 + nc
            int id = t + i * NTHREADS;
            int k = id >> 5, nc = id & 31;
            CPA16(sb + A_BYTES + (uint32_t)k * (SBH * 2) + (uint32_t)nc * 16,
                  wg + (size_t)((size_t)kt * BK + k) * OUTF + nc * 8);
        }
        asm volatile("cp.async.commit_group;" ::: "memory");
    };

    load_tile(0);
    load_tile(1);
    load_tile(2);

    float acc[4][8][4];
#pragma unroll
    for (int mi = 0; mi < 4; mi++)
#pragma unroll
        for (int ni = 0; ni < 8; ni++)
#pragma unroll
            for (int q = 0; q < 4; q++) acc[mi][ni][q] = 0.0f;

    const uint32_t aOff =
        (uint32_t)(wm * 64 + (lane & 7) + ((lane >> 3) & 1) * 8) * (SAH * 2) +
        (uint32_t)((lane >> 4) & 1) * 16;
    const uint32_t bOff = A_BYTES +
        (uint32_t)((lane & 7) + ((lane >> 3) & 1) * 8) * (SBH * 2) +
        (uint32_t)(wn * 64 + ((lane >> 4) & 1) * 8) * 2;

    for (int kt = 0; kt < KT; kt++) {
        asm volatile("cp.async.wait_group 2;" ::: "memory");
        __syncthreads();

        if (kt + 3 < KT) load_tile(kt + 3);
        else asm volatile("cp.async.commit_group;" ::: "memory");

        const uint32_t stage = smb + (uint32_t)(kt & 3) * STAGE_BYTES;

#pragma unroll
        for (int ks = 0; ks < 4; ks++) {   // BK=64 -> 4 x k16
            uint32_t a[4][4], b[4][4];
#pragma unroll
            for (int mi = 0; mi < 4; mi++)
                LDSM_X4(a[mi][0], a[mi][1], a[mi][2], a[mi][3],
                        stage + aOff + (uint32_t)mi * (16 * SAH * 2) + (uint32_t)ks * 32);
#pragma unroll
            for (int np = 0; np < 4; np++)   // 4 x (k16 x n16) = 64 cols
                LDSM_X4T(b[np][0], b[np][1], b[np][2], b[np][3],
                         stage + bOff + (uint32_t)ks * (16 * SBH * 2) + (uint32_t)np * 32);
#pragma unroll
            for (int mi = 0; mi < 4; mi++)
#pragma unroll
                for (int np = 0; np < 4; np++) {
                    mma16816(acc[mi][2 * np],     a[mi], &b[np][0]);
                    mma16816(acc[mi][2 * np + 1], a[mi], &b[np][2]);
                }
        }
    }

    const int r0 = mt * BM + wm * 64 + (lane >> 2);
    const int c0 = nt * BN + wn * 64 + 2 * (lane & 3);
#pragma unroll
    for (int mi = 0; mi < 4; mi++)
#pragma unroll
        for (int ni = 0; ni < 8; ni++) {
            size_t base = (size_t)(r0 + mi * 16) * OUTF + c0 + ni * 8;
            *reinterpret_cast<float2*>(out + base) =
                make_float2(acc[mi][ni][0], acc[mi][ni][1]);
            *reinterpret_cast<float2*>(out + base + 8 * OUTF) =
                make_float2(acc[mi][ni][2], acc[mi][ni][3]);
        }
}

extern "C" void kernel_launch(void* const* d_in, const int* in_sizes, int n_in,
                              void* d_out, int out_size) {
    const float* x = (const float*)d_in[0];
    const float* w = (const float*)d_in[1];
    float* out = (float*)d_out;

    __half* xh = nullptr;
    __half* wh = nullptr;
    cudaGetSymbolAddress((void**)&xh, g_xh);
    cudaGetSymbolAddress((void**)&wh, g_wh);

    cvt_f32_f16<<<4096, 256>>>(x, xh, (size_t)TOK * INF / 8);
    cvt_f32_f16<<<8192, 256>>>(w, wh, (size_t)NG * INF * OUTF / 8);

    cudaFuncSetAttribute(grouped_gemm_f16,
                         cudaFuncAttributeMaxDynamicSharedMemorySize, SMEM_BYTES);
    dim3 grid((TOK / BM) * (OUTF / BN));   // 2048
    grouped_gemm_f16<<<grid, NTHREADS, SMEM_BYTES>>>(out);
}

// round 7
// speedup vs baseline: 3.8214x; 1.1260x over previous
#include <cuda_runtime.h>
#include <cuda_fp16.h>
#include <cstdint>

// Grouped GEMM out[16384,4096]: 8 groups of [2048x4096] @ w[g][4096x4096], fp32 io.
// Pass 1: fp32 -> fp16 scratch (DRAM-bound, ~81% peak, 180us total).
// Pass 2: fp16 HMMA m16n8k16. Round-7 change: 2 CTAs/SM (128x128 tile, 3-stage,
// 107.5KB smem, <=124 regs) so two independent barrier domains interleave --
// fills the ~35% tensor-pipe bubbles measured with occ=1.

#define TOK   16384
#define INF   4096
#define OUTF  4096
#define NG    8

#define BM    128
#define BN    128
#define BK    64
#define KT    (INF / BK)          // 64 k-tiles

#define SAH   72                  // A smem row stride (halves): 144B (bank step +4)
#define SBH   136                 // B smem row stride (halves): 272B (bank step +4)
#define A_BYTES (BM * SAH * 2)    // 18432
#define B_BYTES (BK * SBH * 2)    // 17408
#define STAGE_BYTES (A_BYTES + B_BYTES)       // 35840
#define STAGES 3
#define SMEM_BYTES (STAGES * STAGE_BYTES)     // 107520 -> 2 CTAs/SM
#define NTHREADS 256

__device__ __align__(16) __half g_xh[(size_t)TOK * INF];
__device__ __align__(16) __half g_wh[(size_t)NG * INF * OUTF];

// ---------------- pass 1: fp32 -> fp16 ----------------
__global__ void cvt_f32_f16(const float* __restrict__ src, __half* __restrict__ dst,
                            size_t n8) {
    size_t i = (size_t)blockIdx.x * blockDim.x + threadIdx.x;
    const size_t stride = (size_t)gridDim.x * blockDim.x;
    for (; i < n8; i += stride) {
        float4 v0 = reinterpret_cast<const float4*>(src)[2 * i];
        float4 v1 = reinterpret_cast<const float4*>(src)[2 * i + 1];
        __half2 h0 = __floats2half2_rn(v0.x, v0.y);
        __half2 h1 = __floats2half2_rn(v0.z, v0.w);
        __half2 h2 = __floats2half2_rn(v1.x, v1.y);
        __half2 h3 = __floats2half2_rn(v1.z, v1.w);
        uint4 u;
        u.x = *reinterpret_cast<uint32_t*>(&h0);
        u.y = *reinterpret_cast<uint32_t*>(&h1);
        u.z = *reinterpret_cast<uint32_t*>(&h2);
        u.w = *reinterpret_cast<uint32_t*>(&h3);
        reinterpret_cast<uint4*>(dst)[i] = u;
    }
}

// ---------------- pass 2: fp16 HMMA GEMM ----------------
__device__ __forceinline__ uint32_t smem_u32(const void* p) {
    uint32_t a;
    asm("{ .reg .u64 t; cvta.to.shared.u64 t, %1; cvt.u32.u64 %0, t; }"
        : "=r"(a) : "l"(p));
    return a;
}

#define CPA16(dst, src) \
    asm volatile("cp.async.cg.shared.global [%0], [%1], 16;" :: "r"(dst), "l"(src))

#define LDSM_X4(r0, r1, r2, r3, a)                                              \
    asm volatile("ldmatrix.sync.aligned.m8n8.x4.shared.b16 {%0,%1,%2,%3}, [%4];" \
                 : "=r"(r0), "=r"(r1), "=r"(r2), "=r"(r3) : "r"(a))

#define LDSM_X4T(r0, r1, r2, r3, a)                                                   \
    asm volatile("ldmatrix.sync.aligned.m8n8.x4.trans.shared.b16 {%0,%1,%2,%3}, [%4];" \
                 : "=r"(r0), "=r"(r1), "=r"(r2), "=r"(r3) : "r"(a))

__device__ __forceinline__ void mma16816(float* d, const uint32_t* a, const uint32_t* b) {
    asm volatile(
        "mma.sync.aligned.m16n8k16.row.col.f32.f16.f16.f32 "
        "{%0,%1,%2,%3}, {%4,%5,%6,%7}, {%8,%9}, {%0,%1,%2,%3};"
        : "+f"(d[0]), "+f"(d[1]), "+f"(d[2]), "+f"(d[3])
        : "r"(a[0]), "r"(a[1]), "r"(a[2]), "r"(a[3]), "r"(b[0]), "r"(b[1]));
}

extern "C" __global__ void __launch_bounds__(NTHREADS, 2)
grouped_gemm_f16(float* __restrict__ out) {
    extern __shared__ char sm[];
    const uint32_t smb = smem_u32(sm);

    const int t = threadIdx.x;
    const int lane = t & 31;
    const int wid = t >> 5;          // 8 warps: 2 (m) x 4 (n)
    const int wm = wid & 1;          // 64-row warp tile
    const int wn = wid >> 1;         // 32-col warp tile

    const int bid = blockIdx.x;
    const int nt = bid & 31;         // 32 n-tiles; nt-inner: wave shares A in L2
    const int mt = bid >> 5;         // 128 m-tiles
    const int g  = mt >> 4;

    const __half* xg = g_xh + (size_t)mt * BM * INF;
    const __half* wg = g_wh + (size_t)g * INF * OUTF + (size_t)nt * BN;

    // loader: 256 threads x 8 cp.async (4 A + 4 B), one commit group per k-tile
    auto load_tile = [&](int kt) {
        const uint32_t sb = smb + (uint32_t)((kt % STAGES)) * STAGE_BYTES;
#pragma unroll
        for (int i = 0; i < 4; i++) {           // A: 1024 x 16B; id = row*8 + kc
            int id = t + i * NTHREADS;
            int row = id >> 3, kc = id & 7;
            CPA16(sb + (uint32_t)row * (SAH * 2) + (uint32_t)kc * 16,
                  xg + (size_t)row * INF + (size_t)kt * BK + kc * 8);
        }
#pragma unroll
        for (int i = 0; i < 4; i++) {           // B: 1024 x 16B; id = k*16 + nc
            int id = t + i * NTHREADS;
            int k = id >> 4, nc = id & 15;
            CPA16(sb + A_BYTES + (uint32_t)k * (SBH * 2) + (uint32_t)nc * 16,
                  wg + (size_t)((size_t)kt * BK + k) * OUTF + nc * 8);
        }
        asm volatile("cp.async.commit_group;" ::: "memory");
    };

    load_tile(0);
    load_tile(1);

    float acc[4][4][4];
#pragma unroll
    for (int mi = 0; mi < 4; mi++)
#pragma unroll
        for (int ni = 0; ni < 4; ni++)
#pragma unroll
            for (int q = 0; q < 4; q++) acc[mi][ni][q] = 0.0f;

    // ldmatrix per-lane base byte offsets within a stage
    const uint32_t aOff =
        (uint32_t)(wm * 64 + (lane & 7) + ((lane >> 3) & 1) * 8) * (SAH * 2) +
        (uint32_t)((lane >> 4) & 1) * 16;
    const uint32_t bOff = A_BYTES +
        (uint32_t)((lane & 7) + ((lane >> 3) & 1) * 8) * (SBH * 2) +
        (uint32_t)(wn * 32 + ((lane >> 4) & 1) * 8) * 2;

    for (int kt = 0; kt < KT; kt++) {
        asm volatile("cp.async.wait_group 1;" ::: "memory");   // k-tile kt complete
        __syncthreads();   // tile visible; stage (kt+2)%3's old readers (kt-1) done

        if (kt + 2 < KT) load_tile(kt + 2);
        else asm volatile("cp.async.commit_group;" ::: "memory");  // uniform count

        const uint32_t stage = smb + (uint32_t)(kt % STAGES) * STAGE_BYTES;

#pragma unroll
        for (int ks = 0; ks < 4; ks++) {   // BK=64 -> 4 x k16
            uint32_t a[4][4], b[2][4];
#pragma unroll
            for (int mi = 0; mi < 4; mi++)
                LDSM_X4(a[mi][0], a[mi][1], a[mi][2], a[mi][3],
                        stage + aOff + (uint32_t)mi * (16 * SAH * 2) + (uint32_t)ks * 32);
#pragma unroll
            for (int np = 0; np < 2; np++)   // 2 x (k16 x n16) = 32 cols
                LDSM_X4T(b[np][0], b[np][1], b[np][2], b[np][3],
                         stage + bOff + (uint32_t)ks * (16 * SBH * 2) + (uint32_t)np * 32);
#pragma unroll
            for (int mi = 0; mi < 4; mi++)
#pragma unroll
                for (int np = 0; np < 2; np++) {
                    mma16816(acc[mi][2 * np],     a[mi], &b[np][0]);
                    mma16816(acc[mi][2 * np + 1], a[mi], &b[np][2]);
                }
        }
    }

    const int r0 = mt * BM + wm * 64 + (lane >> 2);
    const int c0 = nt * BN + wn * 32 + 2 * (lane & 3);
#pragma unroll
    for (int mi = 0; mi < 4; mi++)
#pragma unroll
        for (int ni = 0; ni < 4; ni++) {
            size_t base = (size_t)(r0 + mi * 16) * OUTF + c0 + ni * 8;
            *reinterpret_cast<float2*>(out + base) =
                make_float2(acc[mi][ni][0], acc[mi][ni][1]);
            *reinterpret_cast<float2*>(out + base + 8 * OUTF) =
                make_float2(acc[mi][ni][2], acc[mi][ni][3]);
        }
}

extern "C" void kernel_launch(void* const* d_in, const int* in_sizes, int n_in,
                              void* d_out, int out_size) {
    const float* x = (const float*)d_in[0];
    const float* w = (const float*)d_in[1];
    float* out = (float*)d_out;

    __half* xh = nullptr;
    __half* wh = nullptr;
    cudaGetSymbolAddress((void**)&xh, g_xh);
    cudaGetSymbolAddress((void**)&wh, g_wh);

    cvt_f32_f16<<<4096, 256>>>(x, xh, (size_t)TOK * INF / 8);
    cvt_f32_f16<<<8192, 256>>>(w, wh, (size_t)NG * INF * OUTF / 8);

    cudaFuncSetAttribute(grouped_gemm_f16,
                         cudaFuncAttributeMaxDynamicSharedMemorySize, SMEM_BYTES);
    dim3 grid((TOK / BM) * (OUTF / BN));   // 128 * 32 = 4096
    grouped_gemm_f16<<<grid, NTHREADS, SMEM_BYTES>>>(out);
}